// round 16
// baseline (speedup 1.0000x reference)
#include <cuda_runtime.h>
#include <cuda_bf16.h>
#include <cuda_fp16.h>
#include <cstdint>

// Problem sizes (fixed by the reference)
#define PP 16384
#define DD 1024
#define LL 128
#define SPLITK 4
#define BKF 64                         // k-chunk for fp16 syrk

// ---------------------------------------------------------------------------
// Static scratch (no runtime allocation allowed)
// ---------------------------------------------------------------------------
__device__ float g_part[SPLITK][DD * DD];   // split-K partials for big syrk (16 MB)
__device__ float g_m[DD * DD];              // M
__device__ float g_m2[DD * DD];             // M^2
__device__ float g_m4[DD * DD];             // M^4
__device__ float g_m8[DD * DD];             // M^8
__device__ float g_m16[DD * DD];            // M^16
__device__ __half g_sf16[DD * DD];          // Sigma fp16 / scaled deviation fp16 (reused)
__device__ float g_up2[PP / 64][DD];        // partials of X^T y (1 MB)
__device__ unsigned long long g_wt[2][DD];  // tagged chain iterate {tag,val}
__device__ float g_s[DD];                   // accumulated S @ (X^T y)
__device__ __half g_xh[(size_t)DD * PP];    // X^T fp16, [d][p] (32 MB)

// ---------------------------------------------------------------------------
// helpers
// ---------------------------------------------------------------------------
__device__ __forceinline__ uint32_t smem_u32(const void* p) {
    uint32_t a;
    asm("{ .reg .u64 t; cvta.to.shared.u64 t, %1; cvt.u32.u64 %0, t; }" : "=r"(a) : "l"(p));
    return a;
}
#define CP16(dst, src) \
    asm volatile("cp.async.cg.shared.global [%0], [%1], 16;" :: "r"(dst), "l"(src))
#define CP_COMMIT() asm volatile("cp.async.commit_group;" ::: "memory")
#define CP_WAIT0()  asm volatile("cp.async.wait_group 0;" ::: "memory")
#define CP_WAIT1()  asm volatile("cp.async.wait_group 1;" ::: "memory")

#define LDSM4(r0, r1, r2, r3, addr) \
    asm volatile("ldmatrix.sync.aligned.m8n8.x4.shared.b16 {%0,%1,%2,%3}, [%4];" \
        : "=r"(r0), "=r"(r1), "=r"(r2), "=r"(r3) : "r"(addr))
#define MMAF16(c, a, b) \
    asm volatile("mma.sync.aligned.m16n8k16.row.col.f32.f16.f16.f32 " \
        "{%0,%1,%2,%3}, {%4,%5,%6,%7}, {%8,%9}, {%0,%1,%2,%3};" \
        : "+f"((c)[0]), "+f"((c)[1]), "+f"((c)[2]), "+f"((c)[3]) \
        : "r"((a)[0]), "r"((a)[1]), "r"((a)[2]), "r"((a)[3]), "r"((b)[0]), "r"((b)[1]))

// triangular tile index -> (bi, bj), bi <= bj, 8x8 grid
__device__ __forceinline__ void tri_map(int b, int& bi, int& bj) {
    bi = 0; int t = b, rem = 8;
    while (t >= rem) { t -= rem; rem--; bi++; }
    bj = bi + t;
}

// Shared SYRK mainloop: fills acc[4][4][4] for tile (i0, j0) over K range.
// PITCH=144 (128B data + 16B pad), triple-buffered, one barrier per chunk.
// B fragments loaded 2 n-tiles at a time via ldmatrix.x4 (lanes 16-31 take
// the second n-tile's rows): 6 shared-pipe issues per K=16 step instead of 8.
struct SyrkCore {
    template <typename EPI>
    static __device__ void run(char* smem, const __half* A, int pitch, int ksplit,
                               int i0, int j0, int z, EPI epi) {
        const int PITCH = 144, TILE = 128 * PITCH, BUFS = 2 * TILE;
        const int nch = ksplit / BKF;
        int tid = threadIdx.x;
        int wid = tid >> 5, lane = tid & 31;
        int wm = wid >> 2, wn = wid & 3;
        int k_base = z * ksplit;

        float acc[4][4][4];
        #pragma unroll
        for (int mt = 0; mt < 4; mt++)
            #pragma unroll
            for (int nt = 0; nt < 4; nt++)
                #pragma unroll
                for (int q = 0; q < 4; q++) acc[mt][nt][q] = 0.f;

        auto load_chunk = [&](int c, int bsel) {
            int kpos = k_base + c * BKF;
            char* buf = smem + bsel * BUFS;
            #pragma unroll
            for (int q = 0; q < 8; q++) {
                int u = tid + 256 * q;
                int tl = u >> 10;
                int r = (u >> 3) & 127;
                int c16 = u & 7;
                int rowd = (tl ? j0 : i0) + r;
                const char* src = (const char*)(A + (size_t)rowd * pitch + kpos) + c16 * 16;
                uint32_t dst = smem_u32(buf + tl * TILE + r * PITCH + c16 * 16);
                CP16(dst, src);
            }
        };

        auto compute = [&](int bsel) {
            uint32_t base = smem_u32(smem + bsel * BUFS);
            uint32_t abase = base + (wm * 64 + (lane & 15)) * PITCH + (lane >> 4) * 16;
            // B pair-load addressing: lanes 0-15 -> lower n-tile rows,
            // lanes 16-31 -> upper n-tile rows (+8); k-halves via bit 3.
            uint32_t bbase = base + TILE
                           + (wn * 32 + (lane & 7) + ((lane >> 4) & 1) * 8) * PITCH
                           + ((lane >> 3) & 1) * 16;
            #pragma unroll
            for (int ks = 0; ks < BKF / 16; ks++) {
                uint32_t af[4][4];
                uint32_t bf[4][2];
                #pragma unroll
                for (int mt = 0; mt < 4; mt++)
                    LDSM4(af[mt][0], af[mt][1], af[mt][2], af[mt][3],
                          abase + mt * 16 * PITCH + ks * 32);
                #pragma unroll
                for (int p = 0; p < 2; p++)
                    LDSM4(bf[2 * p][0], bf[2 * p][1], bf[2 * p + 1][0], bf[2 * p + 1][1],
                          bbase + p * 16 * PITCH + ks * 32);
                #pragma unroll
                for (int mt = 0; mt < 4; mt++)
                    #pragma unroll
                    for (int nt = 0; nt < 4; nt++)
                        MMAF16(acc[mt][nt], af[mt], bf[nt]);
            }
        };

        load_chunk(0, 0);
        CP_COMMIT();
        for (int c = 0; c < nch; c++) {
            if (c + 1 < nch) {
                load_chunk(c + 1, (c + 1) % 3);
                CP_COMMIT();
                CP_WAIT1();
            } else {
                CP_WAIT0();
            }
            __syncthreads();
            compute(c % 3);
        }
        epi(acc, wm, wn, lane);
    }
};

// ---------------------------------------------------------------------------
// Kernel 0: transpose X -> g_xh[d][p] fp16, fused partial X^T y.
// ---------------------------------------------------------------------------
__global__ void split_kernel(const float* __restrict__ X, const float* __restrict__ y) {
    __shared__ float s[64][65];
    __shared__ float ys[64];
    int p0 = blockIdx.x * 64, d0 = blockIdx.y * 64;
    int t = threadIdx.x;
    if (t < 64) ys[t] = y[p0 + t];
    #pragma unroll
    for (int q = 0; q < 4; q++) {
        int u = t + 256 * q;
        int i = u >> 4, j4 = (u & 15) * 4;
        float4 v = __ldcs((const float4*)&X[(size_t)(p0 + i) * DD + d0 + j4]);
        s[i][j4] = v.x; s[i][j4 + 1] = v.y; s[i][j4 + 2] = v.z; s[i][j4 + 3] = v.w;
    }
    __syncthreads();
    #pragma unroll
    for (int q = 0; q < 8; q++) {
        int u = t + 256 * q;
        int jj = u >> 5, ii = (u & 31) * 2;
        __half2 h = __floats2half2_rn(s[ii][jj], s[ii + 1][jj]);
        *(__half2*)&g_xh[(size_t)(d0 + jj) * PP + p0 + ii] = h;
    }
    if (t < 64) {
        float a = 0.f;
        #pragma unroll 16
        for (int p = 0; p < 64; p++) a += s[p][t] * ys[p];
        g_up2[blockIdx.x][d0 + t] = a;
    }
}

// ---------------------------------------------------------------------------
// Kernel 1: reduce X^T y partials -> tagged w0 (tag=0). grid 4 x 256.
// ---------------------------------------------------------------------------
__global__ void init_kernel() {
    int r = blockIdx.x * 256 + threadIdx.x;
    float acc = 0.f;
    for (int z = 0; z < PP / 64; z++) acc += g_up2[z][r];
    *((volatile unsigned long long*)&g_wt[0][r]) = (unsigned long long)__float_as_uint(acc);
}

// ---------------------------------------------------------------------------
// Kernel 2: big SYRK (Sigma partials): writes g_part[z]. grid (36, 4) x 256.
// ---------------------------------------------------------------------------
__global__ __launch_bounds__(256, 1) void syrk_big(const __half* __restrict__ A) {
    extern __shared__ char smem[];
    int bi, bj; tri_map(blockIdx.x, bi, bj);
    int i0 = bi * 128, j0 = bj * 128;
    bool offdiag = (bi != bj);
    int z = blockIdx.y;
    float* part = g_part[z];

    SyrkCore::run(smem, A, PP, PP / SPLITK, i0, j0, z,
        [&](float (&acc)[4][4][4], int wm, int wn, int lane) {
            int r0 = lane >> 2, c0 = (lane & 3) * 2;
            #pragma unroll
            for (int mt = 0; mt < 4; mt++) {
                int row = i0 + wm * 64 + mt * 16 + r0;
                #pragma unroll
                for (int nt = 0; nt < 4; nt++) {
                    int col = j0 + wn * 32 + nt * 8 + c0;
                    float* a = acc[mt][nt];
                    *(float2*)&part[(size_t)row * DD + col] = make_float2(a[0], a[1]);
                    *(float2*)&part[(size_t)(row + 8) * DD + col] = make_float2(a[2], a[3]);
                    if (offdiag) {
                        part[(size_t)col * DD + row] = a[0];
                        part[(size_t)(col + 1) * DD + row] = a[1];
                        part[(size_t)col * DD + row + 8] = a[2];
                        part[(size_t)(col + 1) * DD + row + 8] = a[3];
                    }
                }
            }
        });
}

// ---------------------------------------------------------------------------
// Kernel 3: SYRK with RED.ADD epilogue: out += scale * (A-rows . A-rows^T).
//  mode 1: scale = c^2 (S = Sigma^2);  mode 2: scale = 2^-26 (S = (E*8192)^2).
// grid (36, SPLITK) x 256; out must be pre-initialized.
// ---------------------------------------------------------------------------
__global__ __launch_bounds__(256, 1) void syrk_red(const __half* __restrict__ A,
                                                   float* __restrict__ outp,
                                                   const float* __restrict__ gamma,
                                                   int mode) {
    extern __shared__ char smem[];
    int bi, bj; tri_map(blockIdx.x, bi, bj);
    int i0 = bi * 128, j0 = bj * 128;
    bool offdiag = (bi != bj);
    int z = blockIdx.y;

    float c = (*gamma) * (1.0f / ((float)LL * (float)PP));
    float sc = (mode == 1) ? c * c : (1.0f / 67108864.0f);

    SyrkCore::run(smem, A, DD, DD / SPLITK, i0, j0, z,
        [&](float (&acc)[4][4][4], int wm, int wn, int lane) {
            int r0 = lane >> 2, c0 = (lane & 3) * 2;
            #pragma unroll
            for (int mt = 0; mt < 4; mt++) {
                int row = i0 + wm * 64 + mt * 16 + r0;
                #pragma unroll
                for (int nt = 0; nt < 4; nt++) {
                    int col = j0 + wn * 32 + nt * 8 + c0;
                    float* a = acc[mt][nt];
                    float v0 = a[0] * sc, v1 = a[1] * sc, v2 = a[2] * sc, v3 = a[3] * sc;
                    atomicAdd(&outp[(size_t)row * DD + col], v0);
                    atomicAdd(&outp[(size_t)row * DD + col + 1], v1);
                    atomicAdd(&outp[(size_t)(row + 8) * DD + col], v2);
                    atomicAdd(&outp[(size_t)(row + 8) * DD + col + 1], v3);
                    if (offdiag) {
                        atomicAdd(&outp[(size_t)col * DD + row], v0);
                        atomicAdd(&outp[(size_t)(col + 1) * DD + row], v1);
                        atomicAdd(&outp[(size_t)col * DD + row + 8], v2);
                        atomicAdd(&outp[(size_t)(col + 1) * DD + row + 8], v3);
                    }
                }
            }
        });
}

// ---------------------------------------------------------------------------
// Kernel 4: reduce Sigma partials: M = I - c*Sigma; Sigma -> fp16;
//           M2_init = 2M - I. grid 512 x 256, two float4 pipelines per thread.
// ---------------------------------------------------------------------------
__global__ __launch_bounds__(256, 4) void reduce0_kernel(const float* __restrict__ gamma) {
    float c = (*gamma) * (1.0f / ((float)LL * (float)PP));
    #pragma unroll
    for (int h = 0; h < 2; h++) {
        int i = blockIdx.x * 512 + threadIdx.x + h * 256;
        float4 r = __ldcs((const float4*)g_part[0] + i);
        #pragma unroll
        for (int z = 1; z < SPLITK; z++) {
            float4 a = __ldcs((const float4*)g_part[z] + i);
            r.x += a.x; r.y += a.y; r.z += a.z; r.w += a.w;
        }
        int e = i * 4, row = e >> 10, col = e & 1023;
        float d0 = (row == col + 0) ? 1.f : 0.f;
        float d1 = (row == col + 1) ? 1.f : 0.f;
        float d2 = (row == col + 2) ? 1.f : 0.f;
        float d3 = (row == col + 3) ? 1.f : 0.f;
        float4 o;
        o.x = d0 - c * r.x; o.y = d1 - c * r.y; o.z = d2 - c * r.z; o.w = d3 - c * r.w;
        __stcs((float4*)g_m + i, o);
        __half2 h0 = __floats2half2_rn(r.x, r.y);
        __half2 h1 = __floats2half2_rn(r.z, r.w);
        uint2 hp = make_uint2(*(uint32_t*)&h0, *(uint32_t*)&h1);
        __stcs((uint2*)&g_sf16[e], hp);
        float4 m2i;
        m2i.x = 2.f * o.x - d0; m2i.y = 2.f * o.y - d1;
        m2i.z = 2.f * o.z - d2; m2i.w = 2.f * o.w - d3;
        ((float4*)g_m2)[i] = m2i;   // read soon by syrk_red: keep cacheable
    }
}

// ---------------------------------------------------------------------------
// Kernel 5: prep for next squaring: E = (Mk - I)*8192 fp16; Mnext = 2Mk - I.
// grid 512 x 256, two float4 pipelines per thread.
// ---------------------------------------------------------------------------
__global__ __launch_bounds__(256, 4) void prep_kernel(const float* __restrict__ Mk,
                                                      float* __restrict__ Mnext) {
    #pragma unroll
    for (int h = 0; h < 2; h++) {
        int i = blockIdx.x * 512 + threadIdx.x + h * 256;
        float4 m = __ldcs((const float4*)Mk + i);
        int e = i * 4, row = e >> 10, col = e & 1023;
        float d0 = (row == col + 0) ? 1.f : 0.f;
        float d1 = (row == col + 1) ? 1.f : 0.f;
        float d2 = (row == col + 2) ? 1.f : 0.f;
        float d3 = (row == col + 3) ? 1.f : 0.f;
        __half2 h0 = __floats2half2_rn((m.x - d0) * 8192.f, (m.y - d1) * 8192.f);
        __half2 h1 = __floats2half2_rn((m.z - d2) * 8192.f, (m.w - d3) * 8192.f);
        uint2 hp = make_uint2(*(uint32_t*)&h0, *(uint32_t*)&h1);
        __stcs((uint2*)&g_sf16[e], hp);
        float4 o;
        o.x = 2.f * m.x - d0; o.y = 2.f * m.y - d1;
        o.z = 2.f * m.z - d2; o.w = 2.f * m.w - d3;
        ((float4*)Mnext)[i] = o;    // read soon by syrk_red: keep cacheable
    }
}

// ---------------------------------------------------------------------------
// Kernel 6: 12-step chain, tagged-data dataflow sync.
// grid 32 x 1024: warp w of block b owns row b*32+w; thread t polls ONE word.
// ---------------------------------------------------------------------------
__global__ __launch_bounds__(1024, 1) void chain_kernel() {
    __shared__ float ws[DD];
    int t = threadIdx.x;
    int wid = t >> 5, lane = t & 31;
    int row = blockIdx.x * 32 + wid;

    const float4* m16row = (const float4*)(g_m16 + (size_t)row * DD);
    float4 a[8];
    #pragma unroll
    for (int i = 0; i < 8; i++) a[i] = m16row[i * 32 + lane];

    float s_acc = 0.f;
    for (int l = 0; l < 12; l++) {
        float4 cur[8];
        if (l < 4) {
            const float* mat = (l == 0) ? g_m : (l == 1) ? g_m2 : (l == 2) ? g_m4 : g_m8;
            const float4* rrow = (const float4*)(mat + (size_t)row * DD);
            #pragma unroll
            for (int i = 0; i < 8; i++) cur[i] = rrow[i * 32 + lane];
        } else {
            #pragma unroll
            for (int i = 0; i < 8; i++) cur[i] = a[i];
        }

        {
            volatile unsigned long long* win = (volatile unsigned long long*)g_wt[l & 1];
            unsigned long long u;
            do { u = win[t]; } while ((unsigned)(u >> 32) != (unsigned)l);
            ws[t] = __uint_as_float((unsigned)u);
        }
        __syncthreads();

        const float4* w4 = (const float4*)ws;
        float dot = 0.f;
        #pragma unroll
        for (int i = 0; i < 8; i++) {
            float4 bv = w4[i * 32 + lane];
            dot += cur[i].x * bv.x + cur[i].y * bv.y + cur[i].z * bv.z + cur[i].w * bv.w;
        }
        #pragma unroll
        for (int o = 16; o; o >>= 1) dot += __shfl_xor_sync(0xffffffffu, dot, o);

        if (lane == 0) {
            float wv = ws[row];
            float outv;
            if (l < 4) outv = wv + dot;              // (I + M^{2^l}) w
            else       { s_acc += wv; outv = dot; }  // accumulate, w' = M^16 w
            unsigned long long u = ((unsigned long long)(unsigned)(l + 1) << 32)
                                 | (unsigned long long)__float_as_uint(outv);
            *((volatile unsigned long long*)&g_wt[(l + 1) & 1][row]) = u;
        }
        __syncthreads();
    }
    if (lane == 0) g_s[row] = s_acc;
}

// ---------------------------------------------------------------------------
// Kernel 7: predictions = (gamma/(L*P)) * (X_star @ s) + bias. grid 2048 x 256.
// ---------------------------------------------------------------------------
__global__ void pred_kernel(const float* __restrict__ Xs,
                            const float* __restrict__ gamma,
                            const float* __restrict__ bias,
                            float* __restrict__ out) {
    __shared__ float ss[DD];
    int t = threadIdx.x;
    #pragma unroll
    for (int i = t; i < DD; i += 256) ss[i] = g_s[i];
    __syncthreads();

    int warp = blockIdx.x * 8 + (t >> 5);
    int lane = t & 31;
    const float4* row4 = (const float4*)(Xs + (size_t)warp * DD);
    const float4* s4 = (const float4*)ss;
    float acc = 0.f;
    #pragma unroll
    for (int j = lane; j < DD / 4; j += 32) {
        float4 a = __ldcs(row4 + j);
        float4 bv = s4[j];
        acc += a.x * bv.x + a.y * bv.y + a.z * bv.z + a.w * bv.w;
    }
    #pragma unroll
    for (int o = 16; o; o >>= 1) acc += __shfl_xor_sync(0xffffffffu, acc, o);
    if (lane == 0) {
        float sc = (*gamma) * (1.0f / ((float)LL * (float)PP));
        out[warp] = sc * acc + (*bias);
    }
}

// ---------------------------------------------------------------------------
extern "C" void kernel_launch(void* const* d_in, const int* in_sizes, int n_in,
                              void* d_out, int out_size) {
    const float* X     = (const float*)d_in[0];
    const float* y     = (const float*)d_in[1];
    const float* Xs    = (const float*)d_in[2];
    const float* gamma = (const float*)d_in[3];
    const float* bias  = (const float*)d_in[4];
    float* out = (float*)d_out;

    const int SMEM_F16 = 3 * 36864;   // 110592 bytes (triple buffer)
    cudaFuncSetAttribute(syrk_big, cudaFuncAttributeMaxDynamicSharedMemorySize, SMEM_F16);
    cudaFuncSetAttribute(syrk_red, cudaFuncAttributeMaxDynamicSharedMemorySize, SMEM_F16);

    __half *xh, *sf;
    cudaGetSymbolAddress((void**)&xh, g_xh);
    cudaGetSymbolAddress((void**)&sf, g_sf16);
    float *pm, *pm2, *pm4, *pm8, *pm16;
    cudaGetSymbolAddress((void**)&pm, g_m);
    cudaGetSymbolAddress((void**)&pm2, g_m2);
    cudaGetSymbolAddress((void**)&pm4, g_m4);
    cudaGetSymbolAddress((void**)&pm8, g_m8);
    cudaGetSymbolAddress((void**)&pm16, g_m16);

    split_kernel<<<dim3(PP / 64, DD / 64), 256>>>(X, y);
    init_kernel<<<4, 256>>>();
    // Sigma partials = X^T X  (fp16 single product, split-K 4)
    syrk_big<<<dim3(36, SPLITK), 256, SMEM_F16>>>(xh);
    // M = I - c*Sigma; Sigma -> fp16; M2 := 2M - I
    reduce0_kernel<<<512, 256>>>(gamma);
    // M2 += c^2 * Sigma^2  (RED.ADD epilogue)
    syrk_red<<<dim3(36, SPLITK), 256, SMEM_F16>>>(sf, pm2, gamma, 1);
    // E2 fp16; M4 := 2*M2 - I
    prep_kernel<<<512, 256>>>(pm2, pm4);
    // M4 += (E2*8192)^2 / 2^26
    syrk_red<<<dim3(36, SPLITK), 256, SMEM_F16>>>(sf, pm4, gamma, 2);
    // E4 fp16; M8 := 2*M4 - I
    prep_kernel<<<512, 256>>>(pm4, pm8);
    syrk_red<<<dim3(36, SPLITK), 256, SMEM_F16>>>(sf, pm8, gamma, 2);
    // E8 fp16; M16 := 2*M8 - I
    prep_kernel<<<512, 256>>>(pm8, pm16);
    syrk_red<<<dim3(36, SPLITK), 256, SMEM_F16>>>(sf, pm16, gamma, 2);
    // 12-step chain + prediction
    chain_kernel<<<32, 1024>>>();
    pred_kernel<<<2048, 256>>>(Xs, gamma, bias, out);
}

// round 17
// speedup vs baseline: 1.0139x; 1.0139x over previous
#include <cuda_runtime.h>
#include <cuda_bf16.h>
#include <cuda_fp16.h>
#include <cstdint>

// Problem sizes (fixed by the reference)
#define PP 16384
#define DD 1024
#define LL 128
#define SPLITK 4

// ---------------------------------------------------------------------------
// Static scratch (no runtime allocation allowed)
// ---------------------------------------------------------------------------
__device__ float g_part[SPLITK][DD * DD];   // split-K partials for big syrk (16 MB)
__device__ float g_m[DD * DD];              // M
__device__ float g_m2[DD * DD];             // M^2
__device__ float g_m4[DD * DD];             // M^4
__device__ float g_m8[DD * DD];             // M^8
__device__ float g_m16[DD * DD];            // M^16
__device__ __half g_sf16[DD * DD];          // Sigma fp16 / scaled deviation fp16 (reused)
__device__ float g_up2[PP / 64][DD];        // partials of X^T y (1 MB)
__device__ unsigned long long g_wt[2][DD];  // tagged chain iterate {tag,val}
__device__ float g_s[DD];                   // accumulated S @ (X^T y)
__device__ __half g_xh[(size_t)DD * PP];    // X^T fp16, [d][p] (32 MB)

// ---------------------------------------------------------------------------
// helpers
// ---------------------------------------------------------------------------
__device__ __forceinline__ uint32_t smem_u32(const void* p) {
    uint32_t a;
    asm("{ .reg .u64 t; cvta.to.shared.u64 t, %1; cvt.u32.u64 %0, t; }" : "=r"(a) : "l"(p));
    return a;
}
#define CP16(dst, src) \
    asm volatile("cp.async.cg.shared.global [%0], [%1], 16;" :: "r"(dst), "l"(src))
#define CP_COMMIT() asm volatile("cp.async.commit_group;" ::: "memory")
#define CP_WAIT0()  asm volatile("cp.async.wait_group 0;" ::: "memory")
#define CP_WAIT1()  asm volatile("cp.async.wait_group 1;" ::: "memory")

#define LDSM4(r, addr) \
    asm volatile("ldmatrix.sync.aligned.m8n8.x4.shared.b16 {%0,%1,%2,%3}, [%4];" \
        : "=r"((r)[0]), "=r"((r)[1]), "=r"((r)[2]), "=r"((r)[3]) : "r"(addr))
#define LDSM2(r, addr) \
    asm volatile("ldmatrix.sync.aligned.m8n8.x2.shared.b16 {%0,%1}, [%2];" \
        : "=r"((r)[0]), "=r"((r)[1]) : "r"(addr))
#define MMAF16(c, a, b) \
    asm volatile("mma.sync.aligned.m16n8k16.row.col.f32.f16.f16.f32 " \
        "{%0,%1,%2,%3}, {%4,%5,%6,%7}, {%8,%9}, {%0,%1,%2,%3};" \
        : "+f"((c)[0]), "+f"((c)[1]), "+f"((c)[2]), "+f"((c)[3]) \
        : "r"((a)[0]), "r"((a)[1]), "r"((a)[2]), "r"((a)[3]), "r"((b)[0]), "r"((b)[1]))

// triangular tile index -> (bi, bj), bi <= bj, 8x8 grid
__device__ __forceinline__ void tri_map(int b, int& bi, int& bj) {
    bi = 0; int t = b, rem = 8;
    while (t >= rem) { t -= rem; rem--; bi++; }
    bj = bi + t;
}

// Shared SYRK mainloop, templated on k-chunk size BK and SMEM row pitch.
// PITCH = BK*2 + 16 (odd multiple of 16B -> conflict-free ldmatrix).
// Triple-buffered, ONE __syncthreads per chunk.
template <int BK, int PITCH>
struct SyrkCore {
    template <typename EPI>
    static __device__ void run(char* smem, const __half* A, int mpitch, int ksplit,
                               int i0, int j0, int z, EPI epi) {
        const int TILE = 128 * PITCH, BUFS = 2 * TILE;
        const int UPT = BK / 8;              // 16B units per tile row
        const int nch = ksplit / BK;
        int tid = threadIdx.x;
        int wid = tid >> 5, lane = tid & 31;
        int wm = wid >> 2, wn = wid & 3;
        int k_base = z * ksplit;

        float acc[4][4][4];
        #pragma unroll
        for (int mt = 0; mt < 4; mt++)
            #pragma unroll
            for (int nt = 0; nt < 4; nt++)
                #pragma unroll
                for (int q = 0; q < 4; q++) acc[mt][nt][q] = 0.f;

        auto load_chunk = [&](int c, int bsel) {
            int kpos = k_base + c * BK;
            char* buf = smem + bsel * BUFS;
            #pragma unroll
            for (int q = 0; q < BK / 8; q++) {
                int u = tid + 256 * q;
                int c16 = u % UPT;
                int r = (u / UPT) % 128;
                int tl = u / (UPT * 128);
                int rowd = (tl ? j0 : i0) + r;
                const char* src = (const char*)(A + (size_t)rowd * mpitch + kpos) + c16 * 16;
                uint32_t dst = smem_u32(buf + tl * TILE + r * PITCH + c16 * 16);
                CP16(dst, src);
            }
        };

        auto compute = [&](int bsel) {
            uint32_t base = smem_u32(smem + bsel * BUFS);
            uint32_t abase = base + (wm * 64 + (lane & 15)) * PITCH + (lane >> 4) * 16;
            uint32_t bbase = base + TILE + (wn * 32 + (lane & 7)) * PITCH + ((lane >> 3) & 1) * 16;
            #pragma unroll
            for (int ks = 0; ks < BK / 16; ks++) {
                uint32_t af[4][4];
                uint32_t bf[4][2];
                #pragma unroll
                for (int mt = 0; mt < 4; mt++)
                    LDSM4(af[mt], abase + mt * 16 * PITCH + ks * 32);
                #pragma unroll
                for (int nt = 0; nt < 4; nt++)
                    LDSM2(bf[nt], bbase + nt * 8 * PITCH + ks * 32);
                #pragma unroll
                for (int mt = 0; mt < 4; mt++)
                    #pragma unroll
                    for (int nt = 0; nt < 4; nt++)
                        MMAF16(acc[mt][nt], af[mt], bf[nt]);
            }
        };

        load_chunk(0, 0);
        CP_COMMIT();
        for (int c = 0; c < nch; c++) {
            if (c + 1 < nch) {
                load_chunk(c + 1, (c + 1) % 3);
                CP_COMMIT();
                CP_WAIT1();
            } else {
                CP_WAIT0();
            }
            __syncthreads();        // single barrier per chunk (triple buffer)
            compute(c % 3);
        }
        epi(acc, wm, wn, lane);
    }
};

// ---------------------------------------------------------------------------
// Kernel 0: transpose X -> g_xh[d][p] fp16, fused partial X^T y.
// ---------------------------------------------------------------------------
__global__ void split_kernel(const float* __restrict__ X, const float* __restrict__ y) {
    __shared__ float s[64][65];
    __shared__ float ys[64];
    int p0 = blockIdx.x * 64, d0 = blockIdx.y * 64;
    int t = threadIdx.x;
    if (t < 64) ys[t] = y[p0 + t];
    #pragma unroll
    for (int q = 0; q < 4; q++) {
        int u = t + 256 * q;
        int i = u >> 4, j4 = (u & 15) * 4;
        float4 v = __ldcs((const float4*)&X[(size_t)(p0 + i) * DD + d0 + j4]);
        s[i][j4] = v.x; s[i][j4 + 1] = v.y; s[i][j4 + 2] = v.z; s[i][j4 + 3] = v.w;
    }
    __syncthreads();
    #pragma unroll
    for (int q = 0; q < 8; q++) {
        int u = t + 256 * q;
        int jj = u >> 5, ii = (u & 31) * 2;
        __half2 h = __floats2half2_rn(s[ii][jj], s[ii + 1][jj]);
        *(__half2*)&g_xh[(size_t)(d0 + jj) * PP + p0 + ii] = h;
    }
    if (t < 64) {
        float a = 0.f;
        #pragma unroll 16
        for (int p = 0; p < 64; p++) a += s[p][t] * ys[p];
        g_up2[blockIdx.x][d0 + t] = a;
    }
}

// ---------------------------------------------------------------------------
// Kernel 1: big SYRK (Sigma partials), BK=128. grid (36, 4) x 256.
// Prologue (overlapped): first 128 blocks reduce X^T y partials -> tagged w0.
// ---------------------------------------------------------------------------
__global__ __launch_bounds__(256, 1) void syrk_big(const __half* __restrict__ A) {
    extern __shared__ char smem[];
    int bi, bj; tri_map(blockIdx.x, bi, bj);
    int i0 = bi * 128, j0 = bj * 128;
    bool offdiag = (bi != bj);
    int z = blockIdx.y;
    float* part = g_part[z];

    // fused init: block bid < 128 reduces 8 rows of X^T y partials (warp per row)
    int bid = blockIdx.y * 36 + blockIdx.x;
    if (bid < 128) {
        int w = threadIdx.x >> 5, lane = threadIdx.x & 31;
        int row = bid * 8 + w;
        float acc = 0.f;
        #pragma unroll
        for (int k = 0; k < 8; k++) acc += g_up2[lane + 32 * k][row];
        #pragma unroll
        for (int o = 16; o; o >>= 1) acc += __shfl_xor_sync(0xffffffffu, acc, o);
        if (lane == 0)
            *((volatile unsigned long long*)&g_wt[0][row]) =
                (unsigned long long)__float_as_uint(acc);
    }

    SyrkCore<128, 272>::run(smem, A, PP, PP / SPLITK, i0, j0, z,
        [&](float (&acc)[4][4][4], int wm, int wn, int lane) {
            int r0 = lane >> 2, c0 = (lane & 3) * 2;
            #pragma unroll
            for (int mt = 0; mt < 4; mt++) {
                int row = i0 + wm * 64 + mt * 16 + r0;
                #pragma unroll
                for (int nt = 0; nt < 4; nt++) {
                    int col = j0 + wn * 32 + nt * 8 + c0;
                    float* a = acc[mt][nt];
                    *(float2*)&part[(size_t)row * DD + col] = make_float2(a[0], a[1]);
                    *(float2*)&part[(size_t)(row + 8) * DD + col] = make_float2(a[2], a[3]);
                    if (offdiag) {
                        part[(size_t)col * DD + row] = a[0];
                        part[(size_t)(col + 1) * DD + row] = a[1];
                        part[(size_t)col * DD + row + 8] = a[2];
                        part[(size_t)(col + 1) * DD + row + 8] = a[3];
                    }
                }
            }
        });
}

// ---------------------------------------------------------------------------
// Kernel 2: SYRK with RED.ADD epilogue: out += scale * (A-rows . A-rows^T).
//  mode 1: scale = c^2 (S = Sigma^2);  mode 2: scale = 2^-26 (S = (E*8192)^2).
// grid (36, SPLITK) x 256; out must be pre-initialized. BK=64.
// ---------------------------------------------------------------------------
__global__ __launch_bounds__(256, 1) void syrk_red(const __half* __restrict__ A,
                                                   float* __restrict__ outp,
                                                   const float* __restrict__ gamma,
                                                   int mode) {
    extern __shared__ char smem[];
    int bi, bj; tri_map(blockIdx.x, bi, bj);
    int i0 = bi * 128, j0 = bj * 128;
    bool offdiag = (bi != bj);
    int z = blockIdx.y;

    float c = (*gamma) * (1.0f / ((float)LL * (float)PP));
    float sc = (mode == 1) ? c * c : (1.0f / 67108864.0f);

    SyrkCore<64, 144>::run(smem, A, DD, DD / SPLITK, i0, j0, z,
        [&](float (&acc)[4][4][4], int wm, int wn, int lane) {
            int r0 = lane >> 2, c0 = (lane & 3) * 2;
            #pragma unroll
            for (int mt = 0; mt < 4; mt++) {
                int row = i0 + wm * 64 + mt * 16 + r0;
                #pragma unroll
                for (int nt = 0; nt < 4; nt++) {
                    int col = j0 + wn * 32 + nt * 8 + c0;
                    float* a = acc[mt][nt];
                    float v0 = a[0] * sc, v1 = a[1] * sc, v2 = a[2] * sc, v3 = a[3] * sc;
                    atomicAdd(&outp[(size_t)row * DD + col], v0);
                    atomicAdd(&outp[(size_t)row * DD + col + 1], v1);
                    atomicAdd(&outp[(size_t)(row + 8) * DD + col], v2);
                    atomicAdd(&outp[(size_t)(row + 8) * DD + col + 1], v3);
                    if (offdiag) {
                        atomicAdd(&outp[(size_t)col * DD + row], v0);
                        atomicAdd(&outp[(size_t)(col + 1) * DD + row], v1);
                        atomicAdd(&outp[(size_t)col * DD + row + 8], v2);
                        atomicAdd(&outp[(size_t)(col + 1) * DD + row + 8], v3);
                    }
                }
            }
        });
}

// ---------------------------------------------------------------------------
// Kernel 3: reduce Sigma partials: M = I - c*Sigma; Sigma -> fp16;
//           M2_init = 2M - I. grid 512 x 256, two float4 pipelines per thread.
// ---------------------------------------------------------------------------
__global__ __launch_bounds__(256, 4) void reduce0_kernel(const float* __restrict__ gamma) {
    float c = (*gamma) * (1.0f / ((float)LL * (float)PP));
    #pragma unroll
    for (int h = 0; h < 2; h++) {
        int i = blockIdx.x * 512 + threadIdx.x + h * 256;
        float4 r = __ldcs((const float4*)g_part[0] + i);
        #pragma unroll
        for (int z = 1; z < SPLITK; z++) {
            float4 a = __ldcs((const float4*)g_part[z] + i);
            r.x += a.x; r.y += a.y; r.z += a.z; r.w += a.w;
        }
        int e = i * 4, row = e >> 10, col = e & 1023;
        float d0 = (row == col + 0) ? 1.f : 0.f;
        float d1 = (row == col + 1) ? 1.f : 0.f;
        float d2 = (row == col + 2) ? 1.f : 0.f;
        float d3 = (row == col + 3) ? 1.f : 0.f;
        float4 o;
        o.x = d0 - c * r.x; o.y = d1 - c * r.y; o.z = d2 - c * r.z; o.w = d3 - c * r.w;
        __stcs((float4*)g_m + i, o);
        __half2 h0 = __floats2half2_rn(r.x, r.y);
        __half2 h1 = __floats2half2_rn(r.z, r.w);
        uint2 hp = make_uint2(*(uint32_t*)&h0, *(uint32_t*)&h1);
        __stcs((uint2*)&g_sf16[e], hp);
        float4 m2i;
        m2i.x = 2.f * o.x - d0; m2i.y = 2.f * o.y - d1;
        m2i.z = 2.f * o.z - d2; m2i.w = 2.f * o.w - d3;
        ((float4*)g_m2)[i] = m2i;   // read soon by syrk_red: keep cacheable
    }
}

// ---------------------------------------------------------------------------
// Kernel 4: prep for next squaring: E = (Mk - I)*8192 fp16; Mnext = 2Mk - I.
// grid 512 x 256, two float4 pipelines per thread.
// ---------------------------------------------------------------------------
__global__ __launch_bounds__(256, 4) void prep_kernel(const float* __restrict__ Mk,
                                                      float* __restrict__ Mnext) {
    #pragma unroll
    for (int h = 0; h < 2; h++) {
        int i = blockIdx.x * 512 + threadIdx.x + h * 256;
        float4 m = __ldcs((const float4*)Mk + i);
        int e = i * 4, row = e >> 10, col = e & 1023;
        float d0 = (row == col + 0) ? 1.f : 0.f;
        float d1 = (row == col + 1) ? 1.f : 0.f;
        float d2 = (row == col + 2) ? 1.f : 0.f;
        float d3 = (row == col + 3) ? 1.f : 0.f;
        __half2 h0 = __floats2half2_rn((m.x - d0) * 8192.f, (m.y - d1) * 8192.f);
        __half2 h1 = __floats2half2_rn((m.z - d2) * 8192.f, (m.w - d3) * 8192.f);
        uint2 hp = make_uint2(*(uint32_t*)&h0, *(uint32_t*)&h1);
        __stcs((uint2*)&g_sf16[e], hp);
        float4 o;
        o.x = 2.f * m.x - d0; o.y = 2.f * m.y - d1;
        o.z = 2.f * m.z - d2; o.w = 2.f * m.w - d3;
        ((float4*)Mnext)[i] = o;    // read soon by syrk_red: keep cacheable
    }
}

// ---------------------------------------------------------------------------
// Kernel 5: 12-step chain, tagged-data dataflow sync.
// grid 32 x 1024: warp w of block b owns row b*32+w; thread t polls ONE word.
// ---------------------------------------------------------------------------
__global__ __launch_bounds__(1024, 1) void chain_kernel() {
    __shared__ float ws[DD];
    int t = threadIdx.x;
    int wid = t >> 5, lane = t & 31;
    int row = blockIdx.x * 32 + wid;

    const float4* m16row = (const float4*)(g_m16 + (size_t)row * DD);
    float4 a[8];
    #pragma unroll
    for (int i = 0; i < 8; i++) a[i] = m16row[i * 32 + lane];

    float s_acc = 0.f;
    for (int l = 0; l < 12; l++) {
        float4 cur[8];
        if (l < 4) {
            const float* mat = (l == 0) ? g_m : (l == 1) ? g_m2 : (l == 2) ? g_m4 : g_m8;
            const float4* rrow = (const float4*)(mat + (size_t)row * DD);
            #pragma unroll
            for (int i = 0; i < 8; i++) cur[i] = rrow[i * 32 + lane];
        } else {
            #pragma unroll
            for (int i = 0; i < 8; i++) cur[i] = a[i];
        }

        {
            volatile unsigned long long* win = (volatile unsigned long long*)g_wt[l & 1];
            unsigned long long u;
            do { u = win[t]; } while ((unsigned)(u >> 32) != (unsigned)l);
            ws[t] = __uint_as_float((unsigned)u);
        }
        __syncthreads();

        const float4* w4 = (const float4*)ws;
        float dot = 0.f;
        #pragma unroll
        for (int i = 0; i < 8; i++) {
            float4 bv = w4[i * 32 + lane];
            dot += cur[i].x * bv.x + cur[i].y * bv.y + cur[i].z * bv.z + cur[i].w * bv.w;
        }
        #pragma unroll
        for (int o = 16; o; o >>= 1) dot += __shfl_xor_sync(0xffffffffu, dot, o);

        if (lane == 0) {
            float wv = ws[row];
            float outv;
            if (l < 4) outv = wv + dot;              // (I + M^{2^l}) w
            else       { s_acc += wv; outv = dot; }  // accumulate, w' = M^16 w
            unsigned long long u = ((unsigned long long)(unsigned)(l + 1) << 32)
                                 | (unsigned long long)__float_as_uint(outv);
            *((volatile unsigned long long*)&g_wt[(l + 1) & 1][row]) = u;
        }
        __syncthreads();
    }
    if (lane == 0) g_s[row] = s_acc;
}

// ---------------------------------------------------------------------------
// Kernel 6: predictions = (gamma/(L*P)) * (X_star @ s) + bias. grid 2048 x 256.
// ---------------------------------------------------------------------------
__global__ void pred_kernel(const float* __restrict__ Xs,
                            const float* __restrict__ gamma,
                            const float* __restrict__ bias,
                            float* __restrict__ out) {
    __shared__ float ss[DD];
    int t = threadIdx.x;
    #pragma unroll
    for (int i = t; i < DD; i += 256) ss[i] = g_s[i];
    __syncthreads();

    int warp = blockIdx.x * 8 + (t >> 5);
    int lane = t & 31;
    const float4* row4 = (const float4*)(Xs + (size_t)warp * DD);
    const float4* s4 = (const float4*)ss;
    float acc = 0.f;
    #pragma unroll
    for (int j = lane; j < DD / 4; j += 32) {
        float4 a = __ldcs(row4 + j);
        float4 bv = s4[j];
        acc += a.x * bv.x + a.y * bv.y + a.z * bv.z + a.w * bv.w;
    }
    #pragma unroll
    for (int o = 16; o; o >>= 1) acc += __shfl_xor_sync(0xffffffffu, acc, o);
    if (lane == 0) {
        float sc = (*gamma) * (1.0f / ((float)LL * (float)PP));
        out[warp] = sc * acc + (*bias);
    }
}

// ---------------------------------------------------------------------------
extern "C" void kernel_launch(void* const* d_in, const int* in_sizes, int n_in,
                              void* d_out, int out_size) {
    const float* X     = (const float*)d_in[0];
    const float* y     = (const float*)d_in[1];
    const float* Xs    = (const float*)d_in[2];
    const float* gamma = (const float*)d_in[3];
    const float* bias  = (const float*)d_in[4];
    float* out = (float*)d_out;

    const int SMEM_BIG = 3 * 2 * 128 * 272;   // 208896 bytes (BK=128, triple buffer)
    const int SMEM_RED = 3 * 2 * 128 * 144;   // 110592 bytes (BK=64, triple buffer)
    cudaFuncSetAttribute(syrk_big, cudaFuncAttributeMaxDynamicSharedMemorySize, SMEM_BIG);
    cudaFuncSetAttribute(syrk_red, cudaFuncAttributeMaxDynamicSharedMemorySize, SMEM_RED);

    __half *xh, *sf;
    cudaGetSymbolAddress((void**)&xh, g_xh);
    cudaGetSymbolAddress((void**)&sf, g_sf16);
    float *pm, *pm2, *pm4, *pm8, *pm16;
    cudaGetSymbolAddress((void**)&pm, g_m);
    cudaGetSymbolAddress((void**)&pm2, g_m2);
    cudaGetSymbolAddress((void**)&pm4, g_m4);
    cudaGetSymbolAddress((void**)&pm8, g_m8);
    cudaGetSymbolAddress((void**)&pm16, g_m16);

    split_kernel<<<dim3(PP / 64, DD / 64), 256>>>(X, y);
    // Sigma partials = X^T X (BK=128) + fused X^T y reduction -> tagged w0
    syrk_big<<<dim3(36, SPLITK), 256, SMEM_BIG>>>(xh);
    // M = I - c*Sigma; Sigma -> fp16; M2 := 2M - I
    reduce0_kernel<<<512, 256>>>(gamma);
    // M2 += c^2 * Sigma^2  (RED.ADD epilogue)
    syrk_red<<<dim3(36, SPLITK), 256, SMEM_RED>>>(sf, pm2, gamma, 1);
    // E2 fp16; M4 := 2*M2 - I
    prep_kernel<<<512, 256>>>(pm2, pm4);
    // M4 += (E2*8192)^2 / 2^26
    syrk_red<<<dim3(36, SPLITK), 256, SMEM_RED>>>(sf, pm4, gamma, 2);
    // E4 fp16; M8 := 2*M4 - I
    prep_kernel<<<512, 256>>>(pm4, pm8);
    syrk_red<<<dim3(36, SPLITK), 256, SMEM_RED>>>(sf, pm8, gamma, 2);
    // E8 fp16; M16 := 2*M8 - I
    prep_kernel<<<512, 256>>>(pm8, pm16);
    syrk_red<<<dim3(36, SPLITK), 256, SMEM_RED>>>(sf, pm16, gamma, 2);
    // 12-step chain + prediction
    chain_kernel<<<32, 1024>>>();
    pred_kernel<<<2048, 256>>>(Xs, gamma, bias, out);
}